// round 9
// baseline (speedup 1.0000x reference)
#include <cuda_runtime.h>
#include <cstdint>
#include <math.h>

// AttentionAggregator, two-kernel pipeline:
//   K1 (tiny): per row, resolve uid = unique_ids[neigh_idx] and the
//       duplicate-column mask (dense mask's .set(1.0) counts repeated cols
//       once; dedup is on cols, computed here, so the hot kernel never sees
//       the 2-deep index chain or the 20 scalar gathers).
//   K2 (hot):  R7 structure — 2 rows/warp, row A register-resident, row B
//       staged to SMEM via cp.async — but the index phase collapses to one
//       contiguous 80B int4 read of g_uid + an int2 of masks.
// features: [100000, 256] f32; nodes: [4096] i32; unique_ids: [16384] i32;
// neigh_idx: [4096, 10] i32. out: [4096, 256] f32.

#define N_NODES 4096
#define FDIM    256
#define NSAMP   10
#define WARPS_PER_BLOCK 4
#define ROWS_PER_BLOCK  (WARPS_PER_BLOCK * 2)
#define SM_ROW_F4 64
#define SM_WARP_F4 ((1 + NSAMP) * SM_ROW_F4)

__device__ int g_uid[N_NODES * NSAMP];   // resolved vocab ids
__device__ int g_dup[N_NODES];           // per-row duplicate-column bitmask

// ---------------- kernel 1: index resolve + dedup ----------------
__global__ void resolve_kernel(const int* __restrict__ uids,
                               const int* __restrict__ nidx)
{
    const int row = blockIdx.x * blockDim.x + threadIdx.x;
    if (row >= N_NODES) return;

    int cols[NSAMP];
    #pragma unroll
    for (int s = 0; s < NSAMP; s++)
        cols[s] = nidx[row * NSAMP + s];          // 10 independent loads

    int uid[NSAMP];
    #pragma unroll
    for (int s = 0; s < NSAMP; s++)
        uid[s] = uids[cols[s]];                   // 10 independent gathers

    unsigned dup = 0;
    #pragma unroll
    for (int s = 1; s < NSAMP; s++) {
        bool d = false;
        #pragma unroll
        for (int t = 0; t < NSAMP; t++)
            if (t < s) d |= (cols[t] == cols[s]);
        if (d) dup |= (1u << s);
    }

    #pragma unroll
    for (int s = 0; s < NSAMP; s++)
        g_uid[row * NSAMP + s] = uid[s];
    g_dup[row] = (int)dup;
}

// ---------------- kernel 2: hot gather + softmax + aggregate ----------------
__device__ __forceinline__ void cp_async16(unsigned int dst, const void* src) {
    asm volatile("cp.async.cg.shared.global [%0], [%1], 16;"
                 :: "r"(dst), "l"(src));
}

__global__ __launch_bounds__(WARPS_PER_BLOCK * 32)
void attn_agg_kernel(const float* __restrict__ feat,
                     const int*   __restrict__ nodes,
                     float*       __restrict__ out)
{
    const int warp = threadIdx.x >> 5;
    const int lane = threadIdx.x & 31;
    const int row0 = (blockIdx.x * WARPS_PER_BLOCK + warp) * 2;  // A, B=row0+1

    __shared__ float4 sbuf[WARPS_PER_BLOCK][SM_WARP_F4];   // 45056 B
    float4* wbuf = sbuf[warp];
    const unsigned int sbase = (unsigned int)__cvta_generic_to_shared(wbuf);

    // --- single-level index read: 80B contiguous uid + masks + node pair ---
    int uid[2 * NSAMP];
    {
        const int4* up = (const int4*)(g_uid + (size_t)row0 * NSAMP);
        #pragma unroll
        for (int i = 0; i < 5; i++) {
            int4 v = up[i];
            uid[4*i+0] = v.x; uid[4*i+1] = v.y;
            uid[4*i+2] = v.z; uid[4*i+3] = v.w;
        }
    }
    const int2 dd = *(const int2*)(g_dup + row0);
    const unsigned dupA = (unsigned)dd.x, dupB = (unsigned)dd.y;
    const int2 nn = *(const int2*)(nodes + row0);

    // --- fire row B into SMEM: 22 cp.async per lane, zero regs held ---
    {
        const float* qB = feat + (size_t)nn.y * FDIM;
        cp_async16(sbase + (unsigned int)lane * 16u,        qB + lane * 4);
        cp_async16(sbase + (unsigned int)(lane + 32) * 16u, qB + (lane + 32) * 4);
        #pragma unroll
        for (int s = 0; s < NSAMP; s++) {
            const float* eB = feat + (size_t)uid[NSAMP + s] * FDIM;
            const unsigned int off = sbase + (unsigned int)(1 + s) * 1024u;
            cp_async16(off + (unsigned int)lane * 16u,        eB + lane * 4);
            cp_async16(off + (unsigned int)(lane + 32) * 16u, eB + (lane + 32) * 4);
        }
        asm volatile("cp.async.commit_group;" ::: "memory");
    }

    // --- row A: register-resident (22 independent LDG.128) ---
    const float4* qpA = (const float4*)(feat + (size_t)nn.x * FDIM);
    const float4 qA0 = qpA[lane];
    const float4 qA1 = qpA[lane + 32];

    float4 a0[NSAMP], a1[NSAMP];
    #pragma unroll
    for (int s = 0; s < NSAMP; s++) {
        const float4* ep = (const float4*)(feat + (size_t)uid[s] * FDIM);
        a0[s] = ep[lane];
        a1[s] = ep[lane + 32];
    }

    float dots[NSAMP];
    #pragma unroll
    for (int s = 0; s < NSAMP; s++) {
        float a = a0[s].x*qA0.x + a0[s].y*qA0.y + a0[s].z*qA0.z + a0[s].w*qA0.w
                + a1[s].x*qA1.x + a1[s].y*qA1.y + a1[s].z*qA1.z + a1[s].w*qA1.w;
        #pragma unroll
        for (int o = 16; o; o >>= 1)
            a += __shfl_xor_sync(0xffffffffu, a, o);
        dots[s] = a;
    }

    // softmax A (redundant per lane) + aggregate + store
    {
        float m = -INFINITY;
        #pragma unroll
        for (int s = 0; s < NSAMP; s++)
            if (!((dupA >> s) & 1u)) m = fmaxf(m, dots[s]);
        float sum = 0.f;
        #pragma unroll
        for (int s = 0; s < NSAMP; s++) {
            float e = ((dupA >> s) & 1u) ? 0.f : __expf(dots[s] - m);
            dots[s] = e; sum += e;
        }
        const float inv = 1.f / sum;

        float4 o0 = make_float4(0.f,0.f,0.f,0.f);
        float4 o1 = make_float4(0.f,0.f,0.f,0.f);
        #pragma unroll
        for (int s = 0; s < NSAMP; s++) {
            const float ws = dots[s] * inv;
            o0.x += ws*a0[s].x; o0.y += ws*a0[s].y;
            o0.z += ws*a0[s].z; o0.w += ws*a0[s].w;
            o1.x += ws*a1[s].x; o1.y += ws*a1[s].y;
            o1.z += ws*a1[s].z; o1.w += ws*a1[s].w;
        }
        float4* op = (float4*)(out + (size_t)row0 * FDIM);
        op[lane]      = o0;
        op[lane + 32] = o1;
    }

    // --- row B: compute from SMEM (each lane reads back its own copies) ---
    asm volatile("cp.async.wait_group 0;" ::: "memory");
    __syncwarp();

    const float4 qB0 = wbuf[lane];
    const float4 qB1 = wbuf[lane + 32];

    #pragma unroll
    for (int s = 0; s < NSAMP; s++) {
        const float4 b0 = wbuf[(1 + s) * SM_ROW_F4 + lane];
        const float4 b1 = wbuf[(1 + s) * SM_ROW_F4 + lane + 32];
        float a = b0.x*qB0.x + b0.y*qB0.y + b0.z*qB0.z + b0.w*qB0.w
                + b1.x*qB1.x + b1.y*qB1.y + b1.z*qB1.z + b1.w*qB1.w;
        #pragma unroll
        for (int o = 16; o; o >>= 1)
            a += __shfl_xor_sync(0xffffffffu, a, o);
        dots[s] = a;
    }

    {
        float m = -INFINITY;
        #pragma unroll
        for (int s = 0; s < NSAMP; s++)
            if (!((dupB >> s) & 1u)) m = fmaxf(m, dots[s]);
        float sum = 0.f;
        #pragma unroll
        for (int s = 0; s < NSAMP; s++) {
            float e = ((dupB >> s) & 1u) ? 0.f : __expf(dots[s] - m);
            dots[s] = e; sum += e;
        }
        const float inv = 1.f / sum;

        float4 o0 = make_float4(0.f,0.f,0.f,0.f);
        float4 o1 = make_float4(0.f,0.f,0.f,0.f);
        #pragma unroll
        for (int s = 0; s < NSAMP; s++) {
            const float ws = dots[s] * inv;
            const float4 b0 = wbuf[(1 + s) * SM_ROW_F4 + lane];
            const float4 b1 = wbuf[(1 + s) * SM_ROW_F4 + lane + 32];
            o0.x += ws*b0.x; o0.y += ws*b0.y;
            o0.z += ws*b0.z; o0.w += ws*b0.w;
            o1.x += ws*b1.x; o1.y += ws*b1.y;
            o1.z += ws*b1.z; o1.w += ws*b1.w;
        }
        float4* op = (float4*)(out + (size_t)(row0 + 1) * FDIM);
        op[lane]      = o0;
        op[lane + 32] = o1;
    }
}

extern "C" void kernel_launch(void* const* d_in, const int* in_sizes, int n_in,
                              void* d_out, int out_size)
{
    const float* feat  = (const float*)d_in[0];
    const int*   nodes = (const int*)  d_in[1];
    const int*   uids  = (const int*)  d_in[2];
    const int*   nidx  = (const int*)  d_in[3];
    float*       out   = (float*)d_out;
    (void)in_sizes; (void)n_in; (void)out_size;

    resolve_kernel<<<(N_NODES + 255) / 256, 256>>>(uids, nidx);
    attn_agg_kernel<<<N_NODES / ROWS_PER_BLOCK, WARPS_PER_BLOCK * 32>>>(
        feat, nodes, out);
}

// round 10
// speedup vs baseline: 1.1831x; 1.1831x over previous
#include <cuda_runtime.h>
#include <cstdint>
#include <math.h>

// AttentionAggregator: one warp per block (wave balance), row A register-
// resident, row B staged to SMEM via cp.async. Evidence: dur tracks gathered
// bytes at ~0.25us/MB across all shapes (occupancy/MLP/index-chain all
// falsified as binding), so this round attacks the second-order terms:
// block-granularity wave imbalance (512->2048 blocks), load ordering (row-A
// LDGs before row-B cp.asyncs), and streaming output stores.
// features: [100000, 256] f32; nodes: [4096] i32; unique_ids: [16384] i32;
// neigh_idx: [4096, 10] i32. out: [4096, 256] f32.

#define N_NODES 4096
#define FDIM    256
#define NSAMP   10
#define SM_ROW_F4 64
#define SM_WARP_F4 ((1 + NSAMP) * SM_ROW_F4)   // q_B + 10 embed rows = 11264 B

__device__ __forceinline__ void cp_async16(unsigned int dst, const void* src) {
    asm volatile("cp.async.cg.shared.global [%0], [%1], 16;"
                 :: "r"(dst), "l"(src));
}

__device__ __forceinline__ void stcs128(float* p, float4 v) {
    asm volatile("st.global.cs.v4.f32 [%0], {%1,%2,%3,%4};"
                 :: "l"(p), "f"(v.x), "f"(v.y), "f"(v.z), "f"(v.w));
}

__global__ __launch_bounds__(32)
void attn_agg_kernel(const float* __restrict__ feat,
                     const int*   __restrict__ nodes,
                     const int*   __restrict__ uids,
                     const int*   __restrict__ nidx,
                     float*       __restrict__ out)
{
    const int lane = threadIdx.x & 31;
    const int row0 = blockIdx.x * 2;              // A=row0, B=row0+1

    __shared__ float4 wbuf[SM_WARP_F4];
    const unsigned int sbase = (unsigned int)__cvta_generic_to_shared(wbuf);

    // --- indices for BOTH rows, issued together (80B contiguous nidx) ---
    int cols[2 * NSAMP];
    {
        const int4* np = (const int4*)(nidx + (size_t)row0 * NSAMP);
        #pragma unroll
        for (int i = 0; i < 5; i++) {
            int4 v = np[i];
            cols[4*i+0] = v.x; cols[4*i+1] = v.y;
            cols[4*i+2] = v.z; cols[4*i+3] = v.w;
        }
    }
    int uid[2 * NSAMP];
    #pragma unroll
    for (int s = 0; s < 2 * NSAMP; s++)
        uid[s] = uids[cols[s]];

    const int2 nn = *(const int2*)(nodes + row0);

    // --- row A FIRST: 22 independent LDG.128 (its latency clock starts now) ---
    const float4* qpA = (const float4*)(feat + (size_t)nn.x * FDIM);
    const float4 qA0 = qpA[lane];
    const float4 qA1 = qpA[lane + 32];

    float4 a0[NSAMP], a1[NSAMP];
    #pragma unroll
    for (int s = 0; s < NSAMP; s++) {
        const float4* ep = (const float4*)(feat + (size_t)uid[s] * FDIM);
        a0[s] = ep[lane];
        a1[s] = ep[lane + 32];
    }

    // --- then fire row B into SMEM: 22 cp.async per lane, zero regs held ---
    {
        const float* qB = feat + (size_t)nn.y * FDIM;
        cp_async16(sbase + (unsigned int)lane * 16u,        qB + lane * 4);
        cp_async16(sbase + (unsigned int)(lane + 32) * 16u, qB + (lane + 32) * 4);
        #pragma unroll
        for (int s = 0; s < NSAMP; s++) {
            const float* eB = feat + (size_t)uid[NSAMP + s] * FDIM;
            const unsigned int off = sbase + (unsigned int)(1 + s) * 1024u;
            cp_async16(off + (unsigned int)lane * 16u,        eB + lane * 4);
            cp_async16(off + (unsigned int)(lane + 32) * 16u, eB + (lane + 32) * 4);
        }
        asm volatile("cp.async.commit_group;" ::: "memory");
    }

    // --- dup masks computed while loads fly (dense mask counts repeats once) ---
    unsigned dup[2] = {0u, 0u};
    #pragma unroll
    for (int r = 0; r < 2; r++)
        #pragma unroll
        for (int s = 1; s < NSAMP; s++) {
            bool d = false;
            #pragma unroll
            for (int t = 0; t < NSAMP; t++)
                if (t < s) d |= (cols[r*NSAMP+t] == cols[r*NSAMP+s]);
            if (d) dup[r] |= (1u << s);
        }

    // --- row A dots + butterfly reduce ---
    float dots[NSAMP];
    #pragma unroll
    for (int s = 0; s < NSAMP; s++) {
        float a = a0[s].x*qA0.x + a0[s].y*qA0.y + a0[s].z*qA0.z + a0[s].w*qA0.w
                + a1[s].x*qA1.x + a1[s].y*qA1.y + a1[s].z*qA1.z + a1[s].w*qA1.w;
        #pragma unroll
        for (int o = 16; o; o >>= 1)
            a += __shfl_xor_sync(0xffffffffu, a, o);
        dots[s] = a;
    }

    // softmax A (redundant per lane) + aggregate + streaming store
    {
        float m = -INFINITY;
        #pragma unroll
        for (int s = 0; s < NSAMP; s++)
            if (!((dup[0] >> s) & 1u)) m = fmaxf(m, dots[s]);
        float sum = 0.f;
        #pragma unroll
        for (int s = 0; s < NSAMP; s++) {
            float e = ((dup[0] >> s) & 1u) ? 0.f : __expf(dots[s] - m);
            dots[s] = e; sum += e;
        }
        const float inv = 1.f / sum;

        float4 o0 = make_float4(0.f,0.f,0.f,0.f);
        float4 o1 = make_float4(0.f,0.f,0.f,0.f);
        #pragma unroll
        for (int s = 0; s < NSAMP; s++) {
            const float ws = dots[s] * inv;
            o0.x += ws*a0[s].x; o0.y += ws*a0[s].y;
            o0.z += ws*a0[s].z; o0.w += ws*a0[s].w;
            o1.x += ws*a1[s].x; o1.y += ws*a1[s].y;
            o1.z += ws*a1[s].z; o1.w += ws*a1[s].w;
        }
        float* op = out + (size_t)row0 * FDIM;
        stcs128(op + lane * 4, o0);
        stcs128(op + (lane + 32) * 4, o1);
    }

    // --- row B: compute from SMEM (each lane reads back its own copies) ---
    asm volatile("cp.async.wait_group 0;" ::: "memory");
    __syncwarp();

    const float4 qB0 = wbuf[lane];
    const float4 qB1 = wbuf[lane + 32];

    #pragma unroll
    for (int s = 0; s < NSAMP; s++) {
        const float4 b0 = wbuf[(1 + s) * SM_ROW_F4 + lane];
        const float4 b1 = wbuf[(1 + s) * SM_ROW_F4 + lane + 32];
        float a = b0.x*qB0.x + b0.y*qB0.y + b0.z*qB0.z + b0.w*qB0.w
                + b1.x*qB1.x + b1.y*qB1.y + b1.z*qB1.z + b1.w*qB1.w;
        #pragma unroll
        for (int o = 16; o; o >>= 1)
            a += __shfl_xor_sync(0xffffffffu, a, o);
        dots[s] = a;
    }

    {
        float m = -INFINITY;
        #pragma unroll
        for (int s = 0; s < NSAMP; s++)
            if (!((dup[1] >> s) & 1u)) m = fmaxf(m, dots[s]);
        float sum = 0.f;
        #pragma unroll
        for (int s = 0; s < NSAMP; s++) {
            float e = ((dup[1] >> s) & 1u) ? 0.f : __expf(dots[s] - m);
            dots[s] = e; sum += e;
        }
        const float inv = 1.f / sum;

        float4 o0 = make_float4(0.f,0.f,0.f,0.f);
        float4 o1 = make_float4(0.f,0.f,0.f,0.f);
        #pragma unroll
        for (int s = 0; s < NSAMP; s++) {
            const float ws = dots[s] * inv;
            const float4 b0 = wbuf[(1 + s) * SM_ROW_F4 + lane];
            const float4 b1 = wbuf[(1 + s) * SM_ROW_F4 + lane + 32];
            o0.x += ws*b0.x; o0.y += ws*b0.y;
            o0.z += ws*b0.z; o0.w += ws*b0.w;
            o1.x += ws*b1.x; o1.y += ws*b1.y;
            o1.z += ws*b1.z; o1.w += ws*b1.w;
        }
        float* op = out + (size_t)(row0 + 1) * FDIM;
        stcs128(op + lane * 4, o0);
        stcs128(op + (lane + 32) * 4, o1);
    }
}

extern "C" void kernel_launch(void* const* d_in, const int* in_sizes, int n_in,
                              void* d_out, int out_size)
{
    const float* feat  = (const float*)d_in[0];
    const int*   nodes = (const int*)  d_in[1];
    const int*   uids  = (const int*)  d_in[2];
    const int*   nidx  = (const int*)  d_in[3];
    float*       out   = (float*)d_out;
    (void)in_sizes; (void)n_in; (void)out_size;

    attn_agg_kernel<<<N_NODES / 2, 32>>>(feat, nodes, uids, nidx, out);
}